// round 1
// baseline (speedup 1.0000x reference)
#include <cuda_runtime.h>
#include <math.h>

#define NB 32
#define NA 8400
#define NG 100
#define BA (NB*NA)
#define NBLK3 (33*32)

// device scratch (static globals - allowed; no runtime allocation)
__device__ float         g_clsc[BA];   // per-anchor class cost (-log p)
__device__ unsigned char g_fg[BA];     // per-anchor fg candidate mask
__device__ int           g_cnt[BA];    // per-anchor match count
__device__ float         g_miou[BA];   // matched-pair iou (valid when cnt==1)
__device__ float         g_psum[NBLK3];
__device__ int           g_pcnt[NBLK3];

__device__ __forceinline__ float iou_pair(float gcx,float gcy,float gw,float gh,
                                          float bcx,float bcy,float bw,float bh){
    float tlx = fmaxf(gcx - gw*0.5f, bcx - bw*0.5f);
    float tly = fmaxf(gcy - gh*0.5f, bcy - bh*0.5f);
    float brx = fminf(gcx + gw*0.5f, bcx + bw*0.5f);
    float bry = fminf(gcy + gh*0.5f, bcy + bh*0.5f);
    float iw = fmaxf(brx - tlx, 0.0f);
    float ih = fmaxf(bry - tly, 0.0f);
    float inter = iw*ih;
    float ua = gw*gh + bw*bh - inter + 1e-12f;
    return inter/ua;
}

__device__ __forceinline__ float softplus(float x){
    return fmaxf(x, 0.0f) + log1pf(expf(-fabsf(x)));
}

// Kernel 1: per-anchor fg mask + per-anchor class cost; also zero match counts.
__global__ void k1_fg_clsc(const float* __restrict__ outputs,
                           const float* __restrict__ labels,
                           const float* __restrict__ xs,
                           const float* __restrict__ ys,
                           const float* __restrict__ st){
    __shared__ float slab[NG*5];
    int b = blockIdx.y;
    const float* lb = labels + b*NG*5;
    for (int i = threadIdx.x; i < NG*5; i += blockDim.x) slab[i] = lb[i];
    __syncthreads();
    int a = blockIdx.x*blockDim.x + threadIdx.x;
    if (a >= NA) return;
    float s  = st[a];
    float xc = (xs[a] + 0.5f) * s;
    float yc = (ys[a] + 0.5f) * s;
    float r  = 2.5f * s;
    bool fg = false;
    #pragma unroll 4
    for (int g = 0; g < NG; g++){
        const float* L = slab + g*5;
        float sum = L[0]+L[1]+L[2]+L[3]+L[4];
        if (!(sum > 0.0f)) continue;   // invalid gt
        float gcx=L[1], gcy=L[2], gw=L[3], gh=L[4];
        bool ib = (xc > gcx - gw*0.5f) && (xc < gcx + gw*0.5f) &&
                  (yc > gcy - gh*0.5f) && (yc < gcy + gh*0.5f);
        bool ic = (fabsf(xc-gcx) < r) && (fabsf(yc-gcy) < r);
        if (ib || ic){ fg = true; break; }
    }
    int idx = b*NA + a;
    g_fg[idx]  = fg ? 1 : 0;
    g_cnt[idx] = 0;
    const float* o = outputs + (size_t)idx*6;
    float obj = o[4], cls = o[5];
    float sig_o = 1.0f/(1.0f + expf(-obj));
    float sig_c = 1.0f/(1.0f + expf(-cls));
    float p = sqrtf(sig_c * sig_o);
    g_clsc[idx] = -logf(p + 1e-9f);
}

// Kernel 2: one warp per (b,g). Top-10 ious -> dyn_k; dyn_k lex-smallest (cost,idx)
// among fg anchors -> scatter matches (atomic int count + matched iou).
__global__ void k2_assign(const float* __restrict__ outputs,
                          const float* __restrict__ labels,
                          const float* __restrict__ xs,
                          const float* __restrict__ ys,
                          const float* __restrict__ st){
    int wid  = (blockIdx.x*blockDim.x + threadIdx.x) >> 5;
    int lane = threadIdx.x & 31;
    if (wid >= NB*NG) return;
    int b = wid / NG, g = wid % NG;
    const float* L = labels + (size_t)(b*NG + g)*5;
    float l0=L[0], gcx=L[1], gcy=L[2], gw=L[3], gh=L[4];
    if (!((l0+gcx+gcy+gw+gh) > 0.0f)) return;     // invalid gt: no matches

    const unsigned char* fg = g_fg + b*NA;
    const float* clsc = g_clsc + b*NA;
    const float* ob   = outputs + (size_t)b*NA*6;

    // per-lane sorted lists (fully unrolled -> registers)
    float tc[10]; int ti[10]; float tv[10]; float tu[10];
    #pragma unroll
    for (int k=0;k<10;k++){ tc[k]=3e38f; ti[k]=0x7fffffff; tv[k]=0.0f; tu[k]=0.0f; }

    for (int a = lane; a < NA; a += 32){
        if (!fg[a]) continue;
        float s  = st[a];
        float xc = (xs[a] + 0.5f) * s;
        float yc = (ys[a] + 0.5f) * s;
        float r  = 2.5f * s;
        float2 c2 = *(const float2*)(ob + (size_t)a*6);
        float2 w2 = *(const float2*)(ob + (size_t)a*6 + 2);
        float iou = iou_pair(gcx,gcy,gw,gh, c2.x,c2.y,w2.x,w2.y);
        bool ib = (xc > gcx - gw*0.5f) && (xc < gcx + gw*0.5f) &&
                  (yc > gcy - gh*0.5f) && (yc < gcy + gh*0.5f);
        bool ic = (fabsf(xc-gcx) < r) && (fabsf(yc-gcy) < r);
        bool geo = ib && ic;
        float cost = clsc[a] - 3.0f*logf(iou + 1e-8f) + (geo ? 0.0f : 100000.0f);

        // top-10 largest ious (values only)
        if (iou > tu[9]){
            float v = iou;
            #pragma unroll
            for (int k=0;k<10;k++){
                if (v > tu[k]){ float t = tu[k]; tu[k] = v; v = t; }
            }
        }
        // top-10 lex-smallest (cost, idx), carry iou
        if (cost < tc[9] || (cost == tc[9] && a < ti[9])){
            float cc = cost; int ii = a; float vv = iou;
            #pragma unroll
            for (int k=0;k<10;k++){
                bool lt = (cc < tc[k]) || (cc == tc[k] && ii < ti[k]);
                if (lt){
                    float t0=tc[k]; tc[k]=cc; cc=t0;
                    int   t1=ti[k]; ti[k]=ii; ii=t1;
                    float t2=tv[k]; tv[k]=vv; vv=t2;
                }
            }
        }
    }

    const unsigned FULL = 0xffffffffu;
    // merge ious across lanes: 10 rounds of warp argmax (descending-order sum)
    float su = 0.0f; int pu = 0;
    #pragma unroll
    for (int r = 0; r < 10; r++){
        float bv = (pu < 10) ? tu[pu] : -1.0f;
        int   bl = lane;
        #pragma unroll
        for (int off = 16; off; off >>= 1){
            float ov = __shfl_down_sync(FULL, bv, off);
            int   ol = __shfl_down_sync(FULL, bl, off);
            if (ov > bv){ bv = ov; bl = ol; }
        }
        bv = __shfl_sync(FULL, bv, 0);
        bl = __shfl_sync(FULL, bl, 0);
        if (lane == bl) pu++;
        su += bv;
    }
    int dynk = (int)su;           // truncation matches astype(int32)
    if (dynk < 1) dynk = 1;

    // merge costs: dyn_k rounds of warp lex-argmin; scatter each winner
    int pc = 0;
    for (int r = 0; r < dynk; r++){
        float bc  = (pc < 10) ? tc[pc] : 3e38f;
        int   bi  = (pc < 10) ? ti[pc] : 0x7fffffff;
        float bvv = (pc < 10) ? tv[pc] : 0.0f;
        int   bl  = lane;
        #pragma unroll
        for (int off = 16; off; off >>= 1){
            float oc = __shfl_down_sync(FULL, bc,  off);
            int   oi = __shfl_down_sync(FULL, bi,  off);
            float ov = __shfl_down_sync(FULL, bvv, off);
            int   ol = __shfl_down_sync(FULL, bl,  off);
            if (oc < bc || (oc == bc && oi < bi)){ bc=oc; bi=oi; bvv=ov; bl=ol; }
        }
        bc  = __shfl_sync(FULL, bc,  0);
        bi  = __shfl_sync(FULL, bi,  0);
        bvv = __shfl_sync(FULL, bvv, 0);
        bl  = __shfl_sync(FULL, bl,  0);
        if (bc >= 1e9f) break;    // exhausted real fg entries (real costs < ~1e5+80)
        if (lane == bl) pc++;
        if (lane == 0){
            atomicAdd(&g_cnt[b*NA + bi], 1);
            g_miou[b*NA + bi] = bvv;   // raced only when cnt>1 (then unused)
        }
    }
}

// Kernel 3: per-anchor loss term; cnt>1 anchors recompute best_gt (self-consistent).
// Block-level deterministic partial reduction.
__global__ void k3_loss(const float* __restrict__ outputs,
                        const float* __restrict__ labels,
                        const float* __restrict__ xs,
                        const float* __restrict__ ys,
                        const float* __restrict__ st){
    __shared__ float slab[NG*5];
    __shared__ float ssum[256];
    __shared__ int   scnt[256];
    int b = blockIdx.y;
    const float* lb = labels + b*NG*5;
    for (int i = threadIdx.x; i < NG*5; i += blockDim.x) slab[i] = lb[i];
    __syncthreads();

    int a = blockIdx.x*blockDim.x + threadIdx.x;
    float term = 0.0f;
    int   isfg = 0;
    if (a < NA){
        int idx = b*NA + a;
        int cnt = g_cnt[idx];
        if (cnt >= 1){
            isfg = 1;
            float pred_iou;
            if (cnt == 1){
                pred_iou = g_miou[idx];
            } else {
                // recompute argmin_g cost (first-g on ties)
                float s  = st[a];
                float xc = (xs[a] + 0.5f) * s;
                float yc = (ys[a] + 0.5f) * s;
                float r  = 2.5f * s;
                const float* o = outputs + (size_t)idx*6;
                float bcx=o[0], bcy=o[1], bw=o[2], bh=o[3];
                float cca = g_clsc[idx];
                float bestc = 3e38f; float besti = 0.0f;
                for (int g = 0; g < NG; g++){
                    const float* L = slab + g*5;
                    float sum = L[0]+L[1]+L[2]+L[3]+L[4];
                    if (!(sum > 0.0f)) continue;
                    float gcx=L[1], gcy=L[2], gw=L[3], gh=L[4];
                    float iou = iou_pair(gcx,gcy,gw,gh, bcx,bcy,bw,bh);
                    bool ib = (xc > gcx - gw*0.5f) && (xc < gcx + gw*0.5f) &&
                              (yc > gcy - gh*0.5f) && (yc < gcy + gh*0.5f);
                    bool ic = (fabsf(xc-gcx) < r) && (fabsf(yc-gcy) < r);
                    bool geo = ib && ic;
                    float cost = cca - 3.0f*logf(iou + 1e-8f) + (geo ? 0.0f : 100000.0f);
                    if (cost < bestc){ bestc = cost; besti = iou; }
                }
                pred_iou = besti;
            }
            float x = outputs[(size_t)idx*6 + 5];   // class logit
            float sp_p = softplus(x);
            float sp_n = softplus(-x);
            term = pred_iou*sp_n + (1.0f - pred_iou)*sp_p;
        }
    }
    ssum[threadIdx.x] = term;
    scnt[threadIdx.x] = isfg;
    __syncthreads();
    for (int o = 128; o; o >>= 1){
        if (threadIdx.x < o){
            ssum[threadIdx.x] += ssum[threadIdx.x + o];
            scnt[threadIdx.x] += scnt[threadIdx.x + o];
        }
        __syncthreads();
    }
    if (threadIdx.x == 0){
        int blk = blockIdx.y*gridDim.x + blockIdx.x;
        g_psum[blk] = ssum[0];
        g_pcnt[blk] = scnt[0];
    }
}

// Kernel 4: fixed-order final reduce (deterministic)
__global__ void k4_final(float* __restrict__ out){
    __shared__ float ss[256];
    __shared__ int   sc[256];
    float s = 0.0f; int c = 0;
    for (int i = threadIdx.x; i < NBLK3; i += 256){ s += g_psum[i]; c += g_pcnt[i]; }
    ss[threadIdx.x] = s; sc[threadIdx.x] = c;
    __syncthreads();
    for (int o = 128; o; o >>= 1){
        if (threadIdx.x < o){ ss[threadIdx.x] += ss[threadIdx.x+o]; sc[threadIdx.x] += sc[threadIdx.x+o]; }
        __syncthreads();
    }
    if (threadIdx.x == 0){
        float nf = (float)sc[0];
        if (nf < 1.0f) nf = 1.0f;
        out[0] = ss[0] / nf;
    }
}

extern "C" void kernel_launch(void* const* d_in, const int* in_sizes, int n_in,
                              void* d_out, int out_size){
    const float* outputs = (const float*)d_in[0];  // [32, 8400, 6]
    const float* labels  = (const float*)d_in[1];  // [32, 100, 5]
    const float* xs      = (const float*)d_in[2];  // [1, 8400]
    const float* ys      = (const float*)d_in[3];  // [1, 8400]
    const float* st      = (const float*)d_in[4];  // [1, 8400]

    dim3 ganchor(33, NB);
    k1_fg_clsc<<<ganchor, 256>>>(outputs, labels, xs, ys, st);
    k2_assign<<<(NB*NG + 3)/4, 128>>>(outputs, labels, xs, ys, st);
    k3_loss<<<ganchor, 256>>>(outputs, labels, xs, ys, st);
    k4_final<<<1, 256>>>((float*)d_out);
}

// round 2
// speedup vs baseline: 1.4578x; 1.4578x over previous
#include <cuda_runtime.h>
#include <math.h>

#define NB 32
#define NA 8400
#define NG 100
#define BA (NB*NA)
#define NBLK3 (33*32)

// ---- device scratch (static globals; no runtime allocation) ----
__device__ float         g_clsc[BA];     // per-anchor class cost (fg anchors only)
__device__ int           g_cnt[BA];      // per-anchor match count
__device__ float         g_miou[BA];     // matched-pair iou (valid when cnt==1)
__device__ int           g_nfg[NB];      // per-image fg count
__device__ int           g_cidx[BA];     // compacted: original anchor index
__device__ float4        g_cbox[BA];     // compacted: pred bbox cxcywh
__device__ float4        g_cgeo[BA];     // compacted: xc, yc, r, clsc
__device__ float         g_psum[NBLK3];
__device__ int           g_pcnt[NBLK3];

__device__ __forceinline__ float iou_pair(float gcx,float gcy,float gw,float gh,
                                          float bcx,float bcy,float bw,float bh){
    float tlx = fmaxf(gcx - gw*0.5f, bcx - bw*0.5f);
    float tly = fmaxf(gcy - gh*0.5f, bcy - bh*0.5f);
    float brx = fminf(gcx + gw*0.5f, bcx + bw*0.5f);
    float bry = fminf(gcy + gh*0.5f, bcy + bh*0.5f);
    float iw = fmaxf(brx - tlx, 0.0f);
    float ih = fmaxf(bry - tly, 0.0f);
    float inter = iw*ih;
    float ua = gw*gh + bw*bh - inter + 1e-12f;
    return inter/ua;
}

__device__ __forceinline__ float softplus(float x){
    return fmaxf(x, 0.0f) + log1pf(expf(-fabsf(x)));
}

// Kernel 0: zero per-image fg counters
__global__ void k0_init(){
    if (threadIdx.x < NB) g_nfg[threadIdx.x] = 0;
}

// Kernel 1: per-anchor fg mask + compaction into per-image SoA; zero match counts.
__global__ void k1_fg_compact(const float* __restrict__ outputs,
                              const float* __restrict__ labels,
                              const float* __restrict__ xs,
                              const float* __restrict__ ys,
                              const float* __restrict__ st){
    __shared__ float slab[NG*5];
    __shared__ int wcnt[8];
    __shared__ int wbase[8];
    __shared__ int blkbase;
    int b = blockIdx.y;
    const float* lb = labels + b*NG*5;
    for (int i = threadIdx.x; i < NG*5; i += blockDim.x) slab[i] = lb[i];
    __syncthreads();

    int a = blockIdx.x*blockDim.x + threadIdx.x;
    bool fg = false;
    float xc=0.f, yc=0.f, r=0.f;
    if (a < NA){
        float s  = st[a];
        xc = (xs[a] + 0.5f) * s;
        yc = (ys[a] + 0.5f) * s;
        r  = 2.5f * s;
        #pragma unroll 4
        for (int g = 0; g < NG; g++){
            const float* L = slab + g*5;
            float sum = L[0]+L[1]+L[2]+L[3]+L[4];
            if (!(sum > 0.0f)) continue;
            float gcx=L[1], gcy=L[2], gw=L[3], gh=L[4];
            bool ib = (xc > gcx - gw*0.5f) && (xc < gcx + gw*0.5f) &&
                      (yc > gcy - gh*0.5f) && (yc < gcy + gh*0.5f);
            bool ic = (fabsf(xc-gcx) < r) && (fabsf(yc-gcy) < r);
            if (ib || ic){ fg = true; break; }
        }
        g_cnt[b*NA + a] = 0;
    }

    // block compaction: ballot + popc prefix + one atomic per block
    unsigned ball = __ballot_sync(0xffffffffu, fg);
    int wid = threadIdx.x >> 5, lane = threadIdx.x & 31;
    if (lane == 0) wcnt[wid] = __popc(ball);
    __syncthreads();
    if (threadIdx.x == 0){
        int tot = 0;
        #pragma unroll
        for (int i = 0; i < 8; i++){ wbase[i] = tot; tot += wcnt[i]; }
        blkbase = tot ? atomicAdd(&g_nfg[b], tot) : 0;
    }
    __syncthreads();

    if (fg){
        int idx = b*NA + a;
        const float* o = outputs + (size_t)idx*6;
        float2 c2 = *(const float2*)(o);
        float2 w2 = *(const float2*)(o + 2);
        float2 oc = *(const float2*)(o + 4);   // obj, cls
        float sig_o = 1.0f/(1.0f + expf(-oc.x));
        float sig_c = 1.0f/(1.0f + expf(-oc.y));
        float clsc = -logf(sqrtf(sig_c * sig_o) + 1e-9f);
        g_clsc[idx] = clsc;
        int pos = b*NA + blkbase + wbase[wid] + __popc(ball & ((1u << lane) - 1u));
        g_cidx[pos] = a;
        g_cbox[pos] = make_float4(c2.x, c2.y, w2.x, w2.y);
        g_cgeo[pos] = make_float4(xc, yc, r, clsc);
    }
}

// Kernel 2: one warp per (b,g). Scan compacted fg list only.
__global__ void k2_assign(const float* __restrict__ labels){
    int wid  = (blockIdx.x*blockDim.x + threadIdx.x) >> 5;
    int lane = threadIdx.x & 31;
    if (wid >= NB*NG) return;
    int b = wid / NG, g = wid % NG;
    const float* L = labels + (size_t)(b*NG + g)*5;
    float l0=L[0], gcx=L[1], gcy=L[2], gw=L[3], gh=L[4];
    if (!((l0+gcx+gcy+gw+gh) > 0.0f)) return;     // invalid gt: no matches

    int nfg = g_nfg[b];
    const int*    cidx = g_cidx + b*NA;
    const float4* cbox = g_cbox + b*NA;
    const float4* cgeo = g_cgeo + b*NA;

    float gl = gcx - gw*0.5f, gr_ = gcx + gw*0.5f;
    float gt_ = gcy - gh*0.5f, gb = gcy + gh*0.5f;
    float garea = gw*gh;

    // per-lane sorted lists (constant-index only -> registers)
    float tc[10]; int ti[10]; float tv[10]; float tu[10];
    #pragma unroll
    for (int k=0;k<10;k++){ tc[k]=3e38f; ti[k]=0x7fffffff; tv[k]=0.0f; tu[k]=0.0f; }

    for (int j = lane; j < nfg; j += 32){
        float4 bb = cbox[j];
        float4 ge = cgeo[j];
        int    a  = cidx[j];
        // iou
        float tlx = fmaxf(gl,  bb.x - bb.z*0.5f);
        float tly = fmaxf(gt_, bb.y - bb.w*0.5f);
        float brx = fminf(gr_, bb.x + bb.z*0.5f);
        float bry = fminf(gb,  bb.y + bb.w*0.5f);
        float iw = fmaxf(brx - tlx, 0.0f);
        float ih = fmaxf(bry - tly, 0.0f);
        float inter = iw*ih;
        float iou = inter / (garea + bb.z*bb.w - inter + 1e-12f);
        // geo
        bool ib = (ge.x > gl) && (ge.x < gr_) && (ge.y > gt_) && (ge.y < gb);
        bool ic = (fabsf(ge.x - gcx) < ge.z) && (fabsf(ge.y - gcy) < ge.z);
        bool geo = ib && ic;
        float cost = ge.w - 3.0f*logf(iou + 1e-8f) + (geo ? 0.0f : 100000.0f);

        if (iou > tu[9]){
            float v = iou;
            #pragma unroll
            for (int k=0;k<10;k++){
                if (v > tu[k]){ float t = tu[k]; tu[k] = v; v = t; }
            }
        }
        if (cost < tc[9] || (cost == tc[9] && a < ti[9])){
            float cc = cost; int ii = a; float vv = iou;
            #pragma unroll
            for (int k=0;k<10;k++){
                bool lt = (cc < tc[k]) || (cc == tc[k] && ii < ti[k]);
                if (lt){
                    float t0=tc[k]; tc[k]=cc; cc=t0;
                    int   t1=ti[k]; ti[k]=ii; ii=t1;
                    float t2=tv[k]; tv[k]=vv; vv=t2;
                }
            }
        }
    }

    const unsigned FULL = 0xffffffffu;
    // merge ious: 10 rounds of warp argmax, head-consume + shift (no dynamic idx)
    float su = 0.0f;
    #pragma unroll
    for (int r = 0; r < 10; r++){
        float bv = tu[0];
        int   bl = lane;
        #pragma unroll
        for (int off = 16; off; off >>= 1){
            float ov = __shfl_down_sync(FULL, bv, off);
            int   ol = __shfl_down_sync(FULL, bl, off);
            if (ov > bv){ bv = ov; bl = ol; }
        }
        bv = __shfl_sync(FULL, bv, 0);
        bl = __shfl_sync(FULL, bl, 0);
        if (lane == bl){
            #pragma unroll
            for (int k=0;k<9;k++) tu[k] = tu[k+1];
            tu[9] = 0.0f;
        }
        su += bv;
    }
    int dynk = (int)su;
    if (dynk < 1) dynk = 1;

    // merge costs: dyn_k rounds of warp lex-argmin, head-consume + shift
    for (int r = 0; r < dynk; r++){
        float bc  = tc[0];
        int   bi  = ti[0];
        float bvv = tv[0];
        int   bl  = lane;
        #pragma unroll
        for (int off = 16; off; off >>= 1){
            float oc = __shfl_down_sync(FULL, bc,  off);
            int   oi = __shfl_down_sync(FULL, bi,  off);
            float ov = __shfl_down_sync(FULL, bvv, off);
            int   ol = __shfl_down_sync(FULL, bl,  off);
            if (oc < bc || (oc == bc && oi < bi)){ bc=oc; bi=oi; bvv=ov; bl=ol; }
        }
        bc  = __shfl_sync(FULL, bc,  0);
        bi  = __shfl_sync(FULL, bi,  0);
        bvv = __shfl_sync(FULL, bvv, 0);
        bl  = __shfl_sync(FULL, bl,  0);
        if (bc >= 1e9f) break;   // exhausted real fg entries
        if (lane == bl){
            #pragma unroll
            for (int k=0;k<9;k++){ tc[k]=tc[k+1]; ti[k]=ti[k+1]; tv[k]=tv[k+1]; }
            tc[9] = 3e38f; ti[9] = 0x7fffffff; tv[9] = 0.0f;
        }
        if (lane == 0){
            atomicAdd(&g_cnt[b*NA + bi], 1);
            g_miou[b*NA + bi] = bvv;   // raced only when cnt>1 (then unused)
        }
    }
}

// Kernel 3: per-anchor loss; cnt>1 anchors recompute best_gt (self-consistent).
__global__ void k3_loss(const float* __restrict__ outputs,
                        const float* __restrict__ labels,
                        const float* __restrict__ xs,
                        const float* __restrict__ ys,
                        const float* __restrict__ st){
    __shared__ float slab[NG*5];
    __shared__ float ssum[256];
    __shared__ int   scnt[256];
    int b = blockIdx.y;
    const float* lb = labels + b*NG*5;
    for (int i = threadIdx.x; i < NG*5; i += blockDim.x) slab[i] = lb[i];
    __syncthreads();

    int a = blockIdx.x*blockDim.x + threadIdx.x;
    float term = 0.0f;
    int   isfg = 0;
    if (a < NA){
        int idx = b*NA + a;
        int cnt = g_cnt[idx];
        if (cnt >= 1){
            isfg = 1;
            float pred_iou;
            if (cnt == 1){
                pred_iou = g_miou[idx];
            } else {
                float s  = st[a];
                float xc = (xs[a] + 0.5f) * s;
                float yc = (ys[a] + 0.5f) * s;
                float r  = 2.5f * s;
                const float* o = outputs + (size_t)idx*6;
                float bcx=o[0], bcy=o[1], bw=o[2], bh=o[3];
                float cca = g_clsc[idx];
                float bestc = 3e38f; float besti = 0.0f;
                for (int g = 0; g < NG; g++){
                    const float* L = slab + g*5;
                    float sum = L[0]+L[1]+L[2]+L[3]+L[4];
                    if (!(sum > 0.0f)) continue;
                    float gcx=L[1], gcy=L[2], gw=L[3], gh=L[4];
                    float iou = iou_pair(gcx,gcy,gw,gh, bcx,bcy,bw,bh);
                    bool ib = (xc > gcx - gw*0.5f) && (xc < gcx + gw*0.5f) &&
                              (yc > gcy - gh*0.5f) && (yc < gcy + gh*0.5f);
                    bool ic = (fabsf(xc-gcx) < r) && (fabsf(yc-gcy) < r);
                    bool geo = ib && ic;
                    float cost = cca - 3.0f*logf(iou + 1e-8f) + (geo ? 0.0f : 100000.0f);
                    if (cost < bestc){ bestc = cost; besti = iou; }
                }
                pred_iou = besti;
            }
            float x = outputs[(size_t)idx*6 + 5];
            float sp_p = softplus(x);
            float sp_n = softplus(-x);
            term = pred_iou*sp_n + (1.0f - pred_iou)*sp_p;
        }
    }
    ssum[threadIdx.x] = term;
    scnt[threadIdx.x] = isfg;
    __syncthreads();
    for (int o = 128; o; o >>= 1){
        if (threadIdx.x < o){
            ssum[threadIdx.x] += ssum[threadIdx.x + o];
            scnt[threadIdx.x] += scnt[threadIdx.x + o];
        }
        __syncthreads();
    }
    if (threadIdx.x == 0){
        int blk = blockIdx.y*gridDim.x + blockIdx.x;
        g_psum[blk] = ssum[0];
        g_pcnt[blk] = scnt[0];
    }
}

// Kernel 4: fixed-order final reduce (deterministic)
__global__ void k4_final(float* __restrict__ out){
    __shared__ float ss[256];
    __shared__ int   sc[256];
    float s = 0.0f; int c = 0;
    for (int i = threadIdx.x; i < NBLK3; i += 256){ s += g_psum[i]; c += g_pcnt[i]; }
    ss[threadIdx.x] = s; sc[threadIdx.x] = c;
    __syncthreads();
    for (int o = 128; o; o >>= 1){
        if (threadIdx.x < o){ ss[threadIdx.x] += ss[threadIdx.x+o]; sc[threadIdx.x] += sc[threadIdx.x+o]; }
        __syncthreads();
    }
    if (threadIdx.x == 0){
        float nf = (float)sc[0];
        if (nf < 1.0f) nf = 1.0f;
        out[0] = ss[0] / nf;
    }
}

extern "C" void kernel_launch(void* const* d_in, const int* in_sizes, int n_in,
                              void* d_out, int out_size){
    const float* outputs = (const float*)d_in[0];  // [32, 8400, 6]
    const float* labels  = (const float*)d_in[1];  // [32, 100, 5]
    const float* xs      = (const float*)d_in[2];  // [1, 8400]
    const float* ys      = (const float*)d_in[3];  // [1, 8400]
    const float* st      = (const float*)d_in[4];  // [1, 8400]

    dim3 ganchor(33, NB);
    k0_init<<<1, 32>>>();
    k1_fg_compact<<<ganchor, 256>>>(outputs, labels, xs, ys, st);
    k2_assign<<<(NB*NG + 3)/4, 128>>>(labels);
    k3_loss<<<ganchor, 256>>>(outputs, labels, xs, ys, st);
    k4_final<<<1, 256>>>((float*)d_out);
}